// round 15
// baseline (speedup 1.0000x reference)
#include <cuda_runtime.h>
#include <cuda_bf16.h>
#include <cstdint>
#include <cstddef>

#define NN 8192
#define IC 128
#define OC 16
#define KH 3
#define CPRB 384                        // chunks per rowblock (3 hops x 128 t)
#define TCH  (64 * CPRB)                // 24576 total chunks
#define A_BYTES (128 * 64 * 2)          // 16 KB per (hi|lo) tile
#define BUF_BYTES (2 * A_BYTES)         // 32 KB per stage
#define DYN_SMEM (2 * BUF_BYTES + 1024) // 66560
#define MAXSLOT 1024                    // supports G <= 512

typedef unsigned long long ull;

// B fragments: idx = ((hop*512 + g16)*2 + nt)*32 + lane -> uint4{bh0,bh1,bl0,bl1}
__device__ __align__(16) uint4 g_Bfrag[KH * 512 * 2 * 32];     // 1.5 MB
__device__ __align__(16) float g_seg[MAXSLOT * 128 * OC];      // 8 MB partial slots
__device__ int g_cnt[NN / 128];                                // per-rb chunk count (self-reset)

// ---------- helpers ----------
__device__ __forceinline__ ull pack_dup(float v) {
    ull r; asm("mov.b64 %0, {%1, %1};" : "=l"(r) : "f"(v)); return r;
}
__device__ __forceinline__ void ffma2(ull& d, ull a, ull b) {
    asm("fma.rn.f32x2 %0, %1, %2, %0;" : "+l"(d) : "l"(a), "l"(b));
}
__device__ __forceinline__ ull addf2(ull a, ull b) {
    ull r; asm("add.rn.f32x2 %0, %1, %2;" : "=l"(r) : "l"(a), "l"(b)); return r;
}
__device__ __forceinline__ uint32_t smem_u32(const void* p) {
    uint32_t a;
    asm("{ .reg .u64 t; cvta.to.shared.u64 t, %1; cvt.u32.u64 %0, t; }" : "=r"(a) : "l"(p));
    return a;
}
__device__ __forceinline__ uint32_t sw128(uint32_t off) {
    return off ^ ((off >> 3) & 0x70);
}
// hi = fp32 truncated to bf16 (top 16 bits); lo = rn(v - hi)
__device__ __forceinline__ void split2(float v0, float v1, uint32_t& hi, uint32_t& lo) {
    uint32_t u0 = __float_as_uint(v0), u1 = __float_as_uint(v1);
    asm("prmt.b32 %0, %1, %2, 0x7632;" : "=r"(hi) : "r"(u0), "r"(u1));
    float l0 = v0 - __uint_as_float(u0 & 0xFFFF0000u);
    float l1 = v1 - __uint_as_float(u1 & 0xFFFF0000u);
    asm("cvt.rn.bf16x2.f32 %0, %1, %2;" : "=r"(lo) : "f"(l1), "f"(l0));
}
__device__ __forceinline__ void mma16816(float* d, const uint32_t* a,
                                         uint32_t b0, uint32_t b1) {
    asm volatile(
        "mma.sync.aligned.m16n8k16.row.col.f32.bf16.bf16.f32 "
        "{%0,%1,%2,%3}, {%4,%5,%6,%7}, {%8,%9}, {%0,%1,%2,%3};"
        : "+f"(d[0]), "+f"(d[1]), "+f"(d[2]), "+f"(d[3])
        : "r"(a[0]), "r"(a[1]), "r"(a[2]), "r"(a[3]), "r"(b0), "r"(b1));
}
__device__ __forceinline__ void ldsm4(uint32_t* r, uint32_t addr) {
    asm volatile("ldmatrix.sync.aligned.m8n8.x4.shared.b16 {%0,%1,%2,%3}, [%4];"
                 : "=r"(r[0]), "=r"(r[1]), "=r"(r[2]), "=r"(r[3]) : "r"(addr));
}

// ---------- kernel 1: fused prep (unchanged from R8) ----------
__global__ void __launch_bounds__(256)
prep_kernel(const float* __restrict__ x, const float* __restrict__ w,
            const float* __restrict__ b, const float* __restrict__ attp) {
    __shared__ ull   wsm[IC * OC / 2];
    __shared__ ull   bsm[OC / 2];
    __shared__ float s_supp[64 * OC];
    int tid = threadIdx.x;
    for (int i = tid; i < IC * OC / 2; i += 256) wsm[i] = ((const ull*)w)[i];
    if (tid < OC / 2) bsm[tid] = ((const ull*)b)[tid];
    __syncthreads();

    int rloc = tid >> 2, q = tid & 3;
    int m = blockIdx.x * 64 + rloc;
    ull acc[8];
#pragma unroll
    for (int j = 0; j < 8; j++) acc[j] = 0ull;

    const float4* xr = (const float4*)(x + (size_t)m * IC + q * 32);
    float4 xv[8];
#pragma unroll
    for (int c4 = 0; c4 < 8; c4++) xv[c4] = xr[c4];
#pragma unroll
    for (int c4 = 0; c4 < 8; c4++)
#pragma unroll
        for (int e = 0; e < 4; e++) {
            ull a2 = pack_dup((&xv[c4].x)[e]);
            int c = q * 32 + c4 * 4 + e;
#pragma unroll
            for (int j = 0; j < 8; j++) ffma2(acc[j], a2, wsm[c * 8 + j]);
        }
#pragma unroll
    for (int j = 0; j < 8; j++) {
        acc[j] = addf2(acc[j], __shfl_xor_sync(0xffffffffu, acc[j], 1));
        acc[j] = addf2(acc[j], __shfl_xor_sync(0xffffffffu, acc[j], 2));
    }
    if (q == 0) {
        ull* o = (ull*)(s_supp + rloc * OC);
#pragma unroll
        for (int j = 0; j < 8; j++) o[j] = addf2(acc[j], bsm[j]);
    }
    __syncthreads();

    float p0 = attp[0], p1 = attp[1], p2 = attp[2];
    float mx = fmaxf(p0, fmaxf(p1, p2));
    float e0 = expf(p0 - mx), e1 = expf(p1 - mx), e2 = expf(p2 - mx);
    float inv = 1.0f / (e0 + e1 + e2);
    float attv[KH] = {e0 * inv, e1 * inv, e2 * inv};

    int lane = tid & 31, nt = (tid >> 5) & 1, g16loc = tid >> 6;
    int g16 = blockIdx.x * 4 + g16loc;
    int k0l = g16loc * 16 + (lane & 3) * 2;
    int d   = nt * 8 + (lane >> 2);
    float s00 = s_supp[(k0l + 0) * OC + d];
    float s01 = s_supp[(k0l + 1) * OC + d];
    float s10 = s_supp[(k0l + 8) * OC + d];
    float s11 = s_supp[(k0l + 9) * OC + d];
#pragma unroll
    for (int hop = 0; hop < KH; hop++) {
        float a = attv[hop];
        uint32_t bh0, bl0, bh1, bl1;
        split2(a * s00, a * s01, bh0, bl0);
        split2(a * s10, a * s11, bh1, bl1);
        g_Bfrag[(hop << 15) | (g16 << 6) | (nt << 5) | lane] =
            make_uint4(bh0, bh1, bl0, bl1);
    }
}

// ---------- kernel 2: R8 inner loop + balanced chunk-range decomposition ----------
__global__ void __launch_bounds__(256, 2)
gcn_main(const float* __restrict__ adj, float* __restrict__ out, int G) {
    extern __shared__ char dsm[];
    __shared__ int s_red;
    int tid = threadIdx.x, lane = tid & 31, w = tid >> 5;
    int cid = blockIdx.x;

    int u0 = (int)(((long long)cid * TCH) / G);
    int u1 = (int)(((long long)(cid + 1) * TCH) / G);

    uint32_t sb = (smem_u32(dsm) + 1023u) & ~1023u;
    int lr = w * 16 + (lane & 15);
    uint32_t rowterm = (uint32_t)lr * 128u;
    uint32_t xorv = (uint32_t)(lr & 7) << 4;
    uint32_t lh16 = (uint32_t)(lane >> 4) * 16u;

    float acc[8];
#pragma unroll
    for (int j = 0; j < 8; j++) acc[j] = 0.0f;

    int crow = tid >> 4, cmq = tid & 15;
    const float4* adjf4 = (const float4*)adj;

    // current chunk state
    int rb = u0 / CPRB, cc = u0 % CPRB;
    int hop = cc >> 7, t = cc & 127;

    float4 v[8];
    {   // prologue: stage chunk u0
        const float4* p = adjf4 + (size_t)hop * NN * (NN / 4) +
                          (size_t)(rb * 128 + crow) * (NN / 4) + t * 16 + cmq;
#pragma unroll
        for (int it = 0; it < 8; it++) v[it] = p[(size_t)it * 16 * (NN / 4)];
    }

    int seg = 0, scnt = 0, parity = 0;

#pragma unroll 1
    for (int u = u0; u < u1; u++) {
        uint32_t Ah = sb + (uint32_t)parity * BUF_BYTES;
        uint32_t Al = Ah + A_BYTES;
        parity ^= 1;

        // ---- convert staged chunk into buf ----
#pragma unroll
        for (int it = 0; it < 8; it++) {
            int row = crow + it * 16;
            uint32_t h01, l01, h23, l23;
            split2(v[it].x, v[it].y, h01, l01);
            split2(v[it].z, v[it].w, h23, l23);
            uint32_t sw = sw128((uint32_t)(row * 128 + cmq * 8));
            asm volatile("st.shared.v2.b32 [%0], {%1, %2};"
                         :: "r"(Ah + sw), "r"(h01), "r"(h23) : "memory");
            asm volatile("st.shared.v2.b32 [%0], {%1, %2};"
                         :: "r"(Al + sw), "r"(l01), "r"(l23) : "memory");
        }

        // ---- next chunk state + prefetch ----
        bool last = (u + 1 == u1);
        int nrb = rb, nhop = hop, ntt = t;
        if (!last) {
            if (++ntt == 128) { ntt = 0; if (++nhop == KH) { nhop = 0; nrb++; } }
            const float4* p = adjf4 + (size_t)nhop * NN * (NN / 4) +
                              (size_t)(nrb * 128 + crow) * (NN / 4) + ntt * 16 + cmq;
#pragma unroll
            for (int it = 0; it < 8; it++) v[it] = p[(size_t)it * 16 * (NN / 4)];
        }

        __syncthreads();

        int bbase = ((hop * 512 + t * 4) * 2) * 32 + lane;
#pragma unroll
        for (int kk = 0; kk < 4; kk++) {
            uint32_t off = ((uint32_t)kk * 32u + lh16) ^ xorv;
            uint32_t ah[4], al[4];
            ldsm4(ah, Ah + rowterm + off);
            ldsm4(al, Al + rowterm + off);
            uint4 B0 = __ldg(&g_Bfrag[bbase + (kk * 2 + 0) * 32]);
            uint4 B1 = __ldg(&g_Bfrag[bbase + (kk * 2 + 1) * 32]);
            mma16816(acc,     ah, B0.x, B0.y);
            mma16816(acc,     al, B0.x, B0.y);
            mma16816(acc,     ah, B0.z, B0.w);
            mma16816(acc + 4, ah, B1.x, B1.y);
            mma16816(acc + 4, al, B1.x, B1.y);
            mma16816(acc + 4, ah, B1.z, B1.w);
        }
        scnt++;

        // ---- segment flush (rowblock boundary or range end) ----
        if (last || nrb != rb) {
            int slot = cid * 2 + seg;
            float* gp = g_seg + (size_t)slot * (128 * OC) +
                        (w * 16 + (lane >> 2)) * OC;
            int ocol = (lane & 3) * 2;
#pragma unroll
            for (int nt2 = 0; nt2 < 2; nt2++) {
                *(float2*)(gp + nt2 * 8 + ocol) =
                    make_float2(acc[nt2 * 4 + 0], acc[nt2 * 4 + 1]);
                *(float2*)(gp + 8 * OC + nt2 * 8 + ocol) =
                    make_float2(acc[nt2 * 4 + 2], acc[nt2 * 4 + 3]);
            }
#pragma unroll
            for (int j = 0; j < 8; j++) acc[j] = 0.0f;

            __threadfence();
            __syncthreads();
            if (tid == 0) {
                int old = atomicAdd(&g_cnt[rb], scnt);
                s_red = (old + scnt == CPRB);
            }
            __syncthreads();
            if (s_red) {
                __threadfence();
                int frb = rb;
                float4 a0 = make_float4(0.f, 0.f, 0.f, 0.f);
                float4 a1 = a0;
#pragma unroll 1
                for (int c2 = 0; c2 < G; c2++) {
                    int s = (int)(((long long)c2 * TCH) / G);
                    int e = (int)(((long long)(c2 + 1) * TCH) / G);
                    int rbs = s / CPRB, rbe = (e - 1) / CPRB;
                    if (frb >= rbs && frb <= rbe) {
                        int sl = c2 * 2 + (frb > rbs ? 1 : 0);
                        const float4* bp = (const float4*)(g_seg + (size_t)sl * (128 * OC));
                        float4 p0 = bp[tid], p1 = bp[tid + 256];
                        a0.x += p0.x; a0.y += p0.y; a0.z += p0.z; a0.w += p0.w;
                        a1.x += p1.x; a1.y += p1.y; a1.z += p1.z; a1.w += p1.w;
                    }
                }
                ((float4*)out)[(size_t)frb * 512 + tid] = a0;
                ((float4*)out)[(size_t)frb * 512 + tid + 256] = a1;
                if (tid == 0) g_cnt[frb] = 0;   // self-reset for replay
            }
            seg = 1; scnt = 0;
        }
        rb = nrb; hop = nhop; t = ntt;
    }
}

extern "C" void kernel_launch(void* const* d_in, const int* in_sizes, int n_in,
                              void* d_out, int out_size) {
    const float* x    = (const float*)d_in[0];
    const float* w    = (const float*)d_in[1];
    const float* b    = (const float*)d_in[2];
    const float* adj  = (const float*)d_in[3];
    const float* attp = (const float*)d_in[4];
    float* out = (float*)d_out;

    int nsm = 148;
    cudaDeviceGetAttribute(&nsm, cudaDevAttrMultiProcessorCount, 0);
    int G = 2 * nsm;
    if (G > 512) G = 512;
    if (G > TCH) G = TCH;

    prep_kernel<<<NN / 64, 256>>>(x, w, b, attp);

    cudaFuncSetAttribute(gcn_main, cudaFuncAttributeMaxDynamicSharedMemorySize,
                         DYN_SMEM);
    gcn_main<<<G, 256, DYN_SMEM>>>(adj, out, G);
}

// round 16
// speedup vs baseline: 1.5626x; 1.5626x over previous
#include <cuda_runtime.h>
#include <cuda_bf16.h>
#include <cstdint>
#include <cstddef>

#define NN 8192
#define IC 128
#define OC 16
#define KH 3
#define MSPLIT 4
#define CPH (NN / MSPLIT / 64)          // 32 chunks (of 64 k) per hop per CTA
#define TOTC (KH * CPH)                 // 96
#define A_BYTES (128 * 64 * 2)          // 16 KB per (hi|lo) tile
#define BUF_BYTES (2 * A_BYTES)         // 32 KB per stage
#define DYN_SMEM (2 * BUF_BYTES + 1024) // 66560

typedef unsigned long long ull;

// B fragments: idx = hop<<15 | g16<<6 | nt<<5 | lane -> uint4{bh0,bh1,bl0,bl1}
__device__ __align__(16) uint4 g_Bfrag[KH * 512 * 2 * 32];     // 1.5 MB
__device__ __align__(16) float g_partial[MSPLIT * NN * OC];    // 2 MB
__device__ int g_cnt[NN / 128];                                // self-resetting

// ---------- helpers ----------
__device__ __forceinline__ ull pack_dup(float v) {
    ull r; asm("mov.b64 %0, {%1, %1};" : "=l"(r) : "f"(v)); return r;
}
__device__ __forceinline__ void ffma2(ull& d, ull a, ull b) {
    asm("fma.rn.f32x2 %0, %1, %2, %0;" : "+l"(d) : "l"(a), "l"(b));
}
__device__ __forceinline__ ull addf2(ull a, ull b) {
    ull r; asm("add.rn.f32x2 %0, %1, %2;" : "=l"(r) : "l"(a), "l"(b)); return r;
}
__device__ __forceinline__ uint32_t smem_u32(const void* p) {
    uint32_t a;
    asm("{ .reg .u64 t; cvta.to.shared.u64 t, %1; cvt.u32.u64 %0, t; }" : "=r"(a) : "l"(p));
    return a;
}
__device__ __forceinline__ uint32_t sw128(uint32_t off) {
    return off ^ ((off >> 3) & 0x70);
}
// hi = fp32 truncated to bf16 (top 16 bits); lo = rn(v - hi)
__device__ __forceinline__ void split2(float v0, float v1, uint32_t& hi, uint32_t& lo) {
    uint32_t u0 = __float_as_uint(v0), u1 = __float_as_uint(v1);
    asm("prmt.b32 %0, %1, %2, 0x7632;" : "=r"(hi) : "r"(u0), "r"(u1));
    float l0 = v0 - __uint_as_float(u0 & 0xFFFF0000u);
    float l1 = v1 - __uint_as_float(u1 & 0xFFFF0000u);
    asm("cvt.rn.bf16x2.f32 %0, %1, %2;" : "=r"(lo) : "f"(l1), "f"(l0));
}
__device__ __forceinline__ void mma16816(float* d, const uint32_t* a,
                                         uint32_t b0, uint32_t b1) {
    asm volatile(
        "mma.sync.aligned.m16n8k16.row.col.f32.bf16.bf16.f32 "
        "{%0,%1,%2,%3}, {%4,%5,%6,%7}, {%8,%9}, {%0,%1,%2,%3};"
        : "+f"(d[0]), "+f"(d[1]), "+f"(d[2]), "+f"(d[3])
        : "r"(a[0]), "r"(a[1]), "r"(a[2]), "r"(a[3]), "r"(b0), "r"(b1));
}
__device__ __forceinline__ void ldsm4(uint32_t* r, uint32_t addr) {
    asm volatile("ldmatrix.sync.aligned.m8n8.x4.shared.b16 {%0,%1,%2,%3}, [%4];"
                 : "=r"(r[0]), "=r"(r[1]), "=r"(r[2]), "=r"(r[3]) : "r"(addr));
}

// ---------- kernel 1: fused prep (R8) + PDL trigger ----------
__global__ void __launch_bounds__(256)
prep_kernel(const float* __restrict__ x, const float* __restrict__ w,
            const float* __restrict__ b, const float* __restrict__ attp) {
    __shared__ ull   wsm[IC * OC / 2];
    __shared__ ull   bsm[OC / 2];
    __shared__ float s_supp[64 * OC];
    int tid = threadIdx.x;
    for (int i = tid; i < IC * OC / 2; i += 256) wsm[i] = ((const ull*)w)[i];
    if (tid < OC / 2) bsm[tid] = ((const ull*)b)[tid];
    __syncthreads();

    int rloc = tid >> 2, q = tid & 3;
    int m = blockIdx.x * 64 + rloc;
    ull acc[8];
#pragma unroll
    for (int j = 0; j < 8; j++) acc[j] = 0ull;

    const float4* xr = (const float4*)(x + (size_t)m * IC + q * 32);
    float4 xv[8];
#pragma unroll
    for (int c4 = 0; c4 < 8; c4++) xv[c4] = xr[c4];
#pragma unroll
    for (int c4 = 0; c4 < 8; c4++)
#pragma unroll
        for (int e = 0; e < 4; e++) {
            ull a2 = pack_dup((&xv[c4].x)[e]);
            int c = q * 32 + c4 * 4 + e;
#pragma unroll
            for (int j = 0; j < 8; j++) ffma2(acc[j], a2, wsm[c * 8 + j]);
        }
#pragma unroll
    for (int j = 0; j < 8; j++) {
        acc[j] = addf2(acc[j], __shfl_xor_sync(0xffffffffu, acc[j], 1));
        acc[j] = addf2(acc[j], __shfl_xor_sync(0xffffffffu, acc[j], 2));
    }
    if (q == 0) {
        ull* o = (ull*)(s_supp + rloc * OC);
#pragma unroll
        for (int j = 0; j < 8; j++) o[j] = addf2(acc[j], bsm[j]);
    }
    __syncthreads();

    float p0 = attp[0], p1 = attp[1], p2 = attp[2];
    float mx = fmaxf(p0, fmaxf(p1, p2));
    float e0 = expf(p0 - mx), e1 = expf(p1 - mx), e2 = expf(p2 - mx);
    float inv = 1.0f / (e0 + e1 + e2);
    float attv[KH] = {e0 * inv, e1 * inv, e2 * inv};

    int lane = tid & 31, nt = (tid >> 5) & 1, g16loc = tid >> 6;
    int g16 = blockIdx.x * 4 + g16loc;
    int k0l = g16loc * 16 + (lane & 3) * 2;
    int d   = nt * 8 + (lane >> 2);
    float s00 = s_supp[(k0l + 0) * OC + d];
    float s01 = s_supp[(k0l + 1) * OC + d];
    float s10 = s_supp[(k0l + 8) * OC + d];
    float s11 = s_supp[(k0l + 9) * OC + d];
#pragma unroll
    for (int hop = 0; hop < KH; hop++) {
        float a = attv[hop];
        uint32_t bh0, bl0, bh1, bl1;
        split2(a * s00, a * s01, bh0, bl0);
        split2(a * s10, a * s11, bh1, bl1);
        g_Bfrag[(hop << 15) | (g16 << 6) | (nt << 5) | lane] =
            make_uint4(bh0, bh1, bl0, bl1);
    }

    // PDL: all Bfrag stores for this thread are issued; allow dependents.
    asm volatile("griddepcontrol.launch_dependents;");
}

// ---------- kernel 2: R8 main GEMM + PDL wait after prologue LDGs ----------
__global__ void __launch_bounds__(256, 2)
gcn_main(const float* __restrict__ adj, float* __restrict__ out) {
    extern __shared__ char dsm[];
    __shared__ int s_last;
    int tid = threadIdx.x, lane = tid & 31, w = tid >> 5;
    int rb = blockIdx.x;                  // 64 row blocks of 128
    int ms = blockIdx.y;                  // MSPLIT k-split

    uint32_t sb = (smem_u32(dsm) + 1023u) & ~1023u;
    int lr = w * 16 + (lane & 15);
    uint32_t rowterm = (uint32_t)lr * 128u;
    uint32_t xorv = (uint32_t)(lr & 7) << 4;
    uint32_t lh16 = (uint32_t)(lane >> 4) * 16u;

    float acc[8];
#pragma unroll
    for (int j = 0; j < 8; j++) acc[j] = 0.0f;

    int crow = tid >> 4, cmq = tid & 15;
    const float4* adjf4 = (const float4*)adj;
    size_t rowoff = (size_t)(rb * 128 + crow) * (NN / 4) + (size_t)ms * 512 + cmq;

    float4 v[8];
    {   // prologue LDGs — no dependence on prep's output
        const float4* p = adjf4 + rowoff;
#pragma unroll
        for (int it = 0; it < 8; it++) v[it] = p[(size_t)it * 16 * (NN / 4)];
    }

    // PDL: wait for prep grid completion (Bfrag visible) with LDGs in flight
    asm volatile("griddepcontrol.wait;");

#pragma unroll 1
    for (int c = 0; c < TOTC; c++) {
        int hop = c >> 5, t = c & 31;
        uint32_t Ah = sb + (uint32_t)(c & 1) * BUF_BYTES;
        uint32_t Al = Ah + A_BYTES;

#pragma unroll
        for (int it = 0; it < 8; it++) {
            int row = crow + it * 16;
            uint32_t h01, l01, h23, l23;
            split2(v[it].x, v[it].y, h01, l01);
            split2(v[it].z, v[it].w, h23, l23);
            uint32_t sw = sw128((uint32_t)(row * 128 + cmq * 8));
            asm volatile("st.shared.v2.b32 [%0], {%1, %2};"
                         :: "r"(Ah + sw), "r"(h01), "r"(h23) : "memory");
            asm volatile("st.shared.v2.b32 [%0], {%1, %2};"
                         :: "r"(Al + sw), "r"(l01), "r"(l23) : "memory");
        }

        if (c + 1 < TOTC) {
            int c1 = c + 1;
            int hop1 = c1 >> 5, t1 = c1 & 31;
            const float4* p = adjf4 + (size_t)hop1 * NN * (NN / 4) + rowoff + t1 * 16;
#pragma unroll
            for (int it = 0; it < 8; it++) v[it] = p[(size_t)it * 16 * (NN / 4)];
        }

        __syncthreads();

        int bbase = ((hop * 512 + ms * 128 + t * 4) * 2) * 32 + lane;
#pragma unroll
        for (int kk = 0; kk < 4; kk++) {
            uint32_t off = ((uint32_t)kk * 32u + lh16) ^ xorv;
            uint32_t ah[4], al[4];
            ldsm4(ah, Ah + rowterm + off);
            ldsm4(al, Al + rowterm + off);
            uint4 B0 = __ldg(&g_Bfrag[bbase + (kk * 2 + 0) * 32]);
            uint4 B1 = __ldg(&g_Bfrag[bbase + (kk * 2 + 1) * 32]);
            mma16816(acc,     ah, B0.x, B0.y);
            mma16816(acc,     al, B0.x, B0.y);
            mma16816(acc,     ah, B0.z, B0.w);
            mma16816(acc + 4, ah, B1.x, B1.y);
            mma16816(acc + 4, al, B1.x, B1.y);
            mma16816(acc + 4, ah, B1.z, B1.w);
        }
    }

    // ---- write this CTA's partial ----
    int orow = rb * 128 + w * 16 + (lane >> 2);
    int ocol = (lane & 3) * 2;
    float* gp = g_partial + ((size_t)ms * NN + orow) * OC;
#pragma unroll
    for (int nt = 0; nt < 2; nt++) {
        *(float2*)(gp + nt * 8 + ocol) =
            make_float2(acc[nt * 4 + 0], acc[nt * 4 + 1]);
        *(float2*)(gp + (size_t)8 * OC + nt * 8 + ocol) =
            make_float2(acc[nt * 4 + 2], acc[nt * 4 + 3]);
    }

    // ---- last-arriving CTA for this rowblock sums the MSPLIT partials ----
    __threadfence();
    __syncthreads();
    if (tid == 0) {
        int old = atomicAdd(&g_cnt[rb], 1);
        s_last = (old == MSPLIT - 1);
    }
    __syncthreads();
    if (s_last) {
        __threadfence();
        const float4* base = (const float4*)(g_partial) + (size_t)rb * 128 * (OC / 4);
#pragma unroll
        for (int u = 0; u < 2; u++) {
            int i = tid + u * 256;
            float4 a = base[i];
#pragma unroll
            for (int mc = 1; mc < MSPLIT; mc++) {
                float4 pv = base[(size_t)mc * NN * (OC / 4) + i];
                a.x += pv.x; a.y += pv.y; a.z += pv.z; a.w += pv.w;
            }
            ((float4*)out)[(size_t)rb * 128 * (OC / 4) + i] = a;
        }
        if (tid == 0) g_cnt[rb] = 0;      // self-reset for next graph replay
    }
}

extern "C" void kernel_launch(void* const* d_in, const int* in_sizes, int n_in,
                              void* d_out, int out_size) {
    const float* x    = (const float*)d_in[0];
    const float* w    = (const float*)d_in[1];
    const float* b    = (const float*)d_in[2];
    const float* adj  = (const float*)d_in[3];
    const float* attp = (const float*)d_in[4];
    float* out = (float*)d_out;

    prep_kernel<<<NN / 64, 256>>>(x, w, b, attp);

    cudaFuncSetAttribute(gcn_main, cudaFuncAttributeMaxDynamicSharedMemorySize,
                         DYN_SMEM);

    // PDL launch: gcn_main may start while prep_kernel is still running.
    cudaLaunchConfig_t cfg = {};
    cfg.gridDim = dim3(NN / 128, MSPLIT);
    cfg.blockDim = dim3(256);
    cfg.dynamicSmemBytes = DYN_SMEM;
    cfg.stream = 0;
    cudaLaunchAttribute at[1];
    at[0].id = cudaLaunchAttributeProgrammaticStreamSerialization;
    at[0].val.programmaticStreamSerializationAllowed = 1;
    cfg.attrs = at;
    cfg.numAttrs = 1;
    cudaLaunchKernelEx(&cfg, gcn_main, adj, out);
}

// round 17
// speedup vs baseline: 1.5711x; 1.0055x over previous
#include <cuda_runtime.h>
#include <cuda_bf16.h>
#include <cstdint>
#include <cstddef>

#define NN 8192
#define IC 128
#define OC 16
#define KH 3
#define MSPLIT 4
#define CPH (NN / MSPLIT / 64)          // 32 chunks (of 64 k) per hop per CTA
#define TOTC (KH * CPH)                 // 96
#define A_BYTES (128 * 64 * 2)          // 16 KB per (hi|lo) tile
#define BUF_BYTES (2 * A_BYTES)         // 32 KB per stage
#define DYN_SMEM (2 * BUF_BYTES + 1024) // 66560

typedef unsigned long long ull;

// B fragments: idx = hop<<15 | g16<<6 | nt<<5 | lane -> uint4{bh0,bh1,bl0,bl1}
__device__ __align__(16) uint4 g_Bfrag[KH * 512 * 2 * 32];     // 1.5 MB
__device__ __align__(16) float g_partial[MSPLIT * NN * OC];    // 2 MB
__device__ int g_cnt[NN / 128];                                // self-resetting

// ---------- helpers ----------
__device__ __forceinline__ ull pack_dup(float v) {
    ull r; asm("mov.b64 %0, {%1, %1};" : "=l"(r) : "f"(v)); return r;
}
__device__ __forceinline__ void ffma2(ull& d, ull a, ull b) {
    asm("fma.rn.f32x2 %0, %1, %2, %0;" : "+l"(d) : "l"(a), "l"(b));
}
__device__ __forceinline__ ull addf2(ull a, ull b) {
    ull r; asm("add.rn.f32x2 %0, %1, %2;" : "=l"(r) : "l"(a), "l"(b)); return r;
}
__device__ __forceinline__ uint32_t smem_u32(const void* p) {
    uint32_t a;
    asm("{ .reg .u64 t; cvta.to.shared.u64 t, %1; cvt.u32.u64 %0, t; }" : "=r"(a) : "l"(p));
    return a;
}
__device__ __forceinline__ uint32_t sw128(uint32_t off) {
    return off ^ ((off >> 3) & 0x70);
}
// hi = fp32 truncated to bf16 (top 16 bits); lo = rn(v - hi)
__device__ __forceinline__ void split2(float v0, float v1, uint32_t& hi, uint32_t& lo) {
    uint32_t u0 = __float_as_uint(v0), u1 = __float_as_uint(v1);
    asm("prmt.b32 %0, %1, %2, 0x7632;" : "=r"(hi) : "r"(u0), "r"(u1));
    float l0 = v0 - __uint_as_float(u0 & 0xFFFF0000u);
    float l1 = v1 - __uint_as_float(u1 & 0xFFFF0000u);
    asm("cvt.rn.bf16x2.f32 %0, %1, %2;" : "=r"(lo) : "f"(l1), "f"(l0));
}
__device__ __forceinline__ void mma16816(float* d, const uint32_t* a,
                                         uint32_t b0, uint32_t b1) {
    asm volatile(
        "mma.sync.aligned.m16n8k16.row.col.f32.bf16.bf16.f32 "
        "{%0,%1,%2,%3}, {%4,%5,%6,%7}, {%8,%9}, {%0,%1,%2,%3};"
        : "+f"(d[0]), "+f"(d[1]), "+f"(d[2]), "+f"(d[3])
        : "r"(a[0]), "r"(a[1]), "r"(a[2]), "r"(a[3]), "r"(b0), "r"(b1));
}
__device__ __forceinline__ void ldsm4(uint32_t* r, uint32_t addr) {
    asm volatile("ldmatrix.sync.aligned.m8n8.x4.shared.b16 {%0,%1,%2,%3}, [%4];"
                 : "=r"(r[0]), "=r"(r[1]), "=r"(r[2]), "=r"(r[3]) : "r"(addr));
}

// ---------- kernel 1: fused prep — grid 256 (32 rows/CTA), PDL trigger ----------
__global__ void __launch_bounds__(256)
prep_kernel(const float* __restrict__ x, const float* __restrict__ w,
            const float* __restrict__ b, const float* __restrict__ attp) {
    __shared__ ull   wsm[IC * OC / 2];
    __shared__ ull   bsm[OC / 2];
    __shared__ float s_supp[32 * OC];
    int tid = threadIdx.x;
    for (int i = tid; i < IC * OC / 2; i += 256) wsm[i] = ((const ull*)w)[i];
    if (tid < OC / 2) bsm[tid] = ((const ull*)b)[tid];
    __syncthreads();

    // support for 32 rows: threads 0..127, 4 threads/row (same chain as R8)
    if (tid < 128) {
        int rloc = tid >> 2, q = tid & 3;
        int m = blockIdx.x * 32 + rloc;
        ull acc[8];
#pragma unroll
        for (int j = 0; j < 8; j++) acc[j] = 0ull;

        const float4* xr = (const float4*)(x + (size_t)m * IC + q * 32);
        float4 xv[8];
#pragma unroll
        for (int c4 = 0; c4 < 8; c4++) xv[c4] = xr[c4];
#pragma unroll
        for (int c4 = 0; c4 < 8; c4++)
#pragma unroll
            for (int e = 0; e < 4; e++) {
                ull a2 = pack_dup((&xv[c4].x)[e]);
                int c = q * 32 + c4 * 4 + e;
#pragma unroll
                for (int j = 0; j < 8; j++) ffma2(acc[j], a2, wsm[c * 8 + j]);
            }
#pragma unroll
        for (int j = 0; j < 8; j++) {
            acc[j] = addf2(acc[j], __shfl_xor_sync(0xffffffffu, acc[j], 1));
            acc[j] = addf2(acc[j], __shfl_xor_sync(0xffffffffu, acc[j], 2));
        }
        if (q == 0) {
            ull* o = (ull*)(s_supp + rloc * OC);
#pragma unroll
            for (int j = 0; j < 8; j++) o[j] = addf2(acc[j], bsm[j]);
        }
    }
    __syncthreads();

    float p0 = attp[0], p1 = attp[1], p2 = attp[2];
    float mx = fmaxf(p0, fmaxf(p1, p2));
    float e0 = expf(p0 - mx), e1 = expf(p1 - mx), e2 = expf(p2 - mx);
    float inv = 1.0f / (e0 + e1 + e2);
    float attv[KH] = {e0 * inv, e1 * inv, e2 * inv};

    // B fragments: threads 0..127 -> 2 g16 groups
    if (tid < 128) {
        int lane = tid & 31, nt = (tid >> 5) & 1, g16loc = tid >> 6;   // 0..1
        int g16 = blockIdx.x * 2 + g16loc;
        int k0l = g16loc * 16 + (lane & 3) * 2;
        int d   = nt * 8 + (lane >> 2);
        float s00 = s_supp[(k0l + 0) * OC + d];
        float s01 = s_supp[(k0l + 1) * OC + d];
        float s10 = s_supp[(k0l + 8) * OC + d];
        float s11 = s_supp[(k0l + 9) * OC + d];
#pragma unroll
        for (int hop = 0; hop < KH; hop++) {
            float a = attv[hop];
            uint32_t bh0, bl0, bh1, bl1;
            split2(a * s00, a * s01, bh0, bl0);
            split2(a * s10, a * s11, bh1, bl1);
            g_Bfrag[(hop << 15) | (g16 << 6) | (nt << 5) | lane] =
                make_uint4(bh0, bh1, bl0, bl1);
        }
    }

    // PDL: all Bfrag stores for this thread are issued; allow dependents.
    asm volatile("griddepcontrol.launch_dependents;");
}

// ---------- kernel 2: R8 main GEMM + PDL wait deferred to first Bfrag use ----------
__global__ void __launch_bounds__(256, 2)
gcn_main(const float* __restrict__ adj, float* __restrict__ out) {
    extern __shared__ char dsm[];
    __shared__ int s_last;
    int tid = threadIdx.x, lane = tid & 31, w = tid >> 5;
    int rb = blockIdx.x;                  // 64 row blocks of 128
    int ms = blockIdx.y;                  // MSPLIT k-split

    uint32_t sb = (smem_u32(dsm) + 1023u) & ~1023u;
    int lr = w * 16 + (lane & 15);
    uint32_t rowterm = (uint32_t)lr * 128u;
    uint32_t xorv = (uint32_t)(lr & 7) << 4;
    uint32_t lh16 = (uint32_t)(lane >> 4) * 16u;

    float acc[8];
#pragma unroll
    for (int j = 0; j < 8; j++) acc[j] = 0.0f;

    int crow = tid >> 4, cmq = tid & 15;
    const float4* adjf4 = (const float4*)adj;
    size_t rowoff = (size_t)(rb * 128 + crow) * (NN / 4) + (size_t)ms * 512 + cmq;

    float4 v[8];
    {   // prologue LDGs — no dependence on prep's output
        const float4* p = adjf4 + rowoff;
#pragma unroll
        for (int it = 0; it < 8; it++) v[it] = p[(size_t)it * 16 * (NN / 4)];
    }

#pragma unroll 1
    for (int c = 0; c < TOTC; c++) {
        int hop = c >> 5, t = c & 31;
        uint32_t Ah = sb + (uint32_t)(c & 1) * BUF_BYTES;
        uint32_t Al = Ah + A_BYTES;

#pragma unroll
        for (int it = 0; it < 8; it++) {
            int row = crow + it * 16;
            uint32_t h01, l01, h23, l23;
            split2(v[it].x, v[it].y, h01, l01);
            split2(v[it].z, v[it].w, h23, l23);
            uint32_t sw = sw128((uint32_t)(row * 128 + cmq * 8));
            asm volatile("st.shared.v2.b32 [%0], {%1, %2};"
                         :: "r"(Ah + sw), "r"(h01), "r"(h23) : "memory");
            asm volatile("st.shared.v2.b32 [%0], {%1, %2};"
                         :: "r"(Al + sw), "r"(l01), "r"(l23) : "memory");
        }

        if (c + 1 < TOTC) {
            int c1 = c + 1;
            int hop1 = c1 >> 5, t1 = c1 & 31;
            const float4* p = adjf4 + (size_t)hop1 * NN * (NN / 4) + rowoff + t1 * 16;
#pragma unroll
            for (int it = 0; it < 8; it++) v[it] = p[(size_t)it * 16 * (NN / 4)];
        }

        __syncthreads();

        // PDL: first Bfrag consumption is below; wait as late as legal.
        if (c == 0) asm volatile("griddepcontrol.wait;");

        int bbase = ((hop * 512 + ms * 128 + t * 4) * 2) * 32 + lane;
#pragma unroll
        for (int kk = 0; kk < 4; kk++) {
            uint32_t off = ((uint32_t)kk * 32u + lh16) ^ xorv;
            uint32_t ah[4], al[4];
            ldsm4(ah, Ah + rowterm + off);
            ldsm4(al, Al + rowterm + off);
            uint4 B0 = __ldg(&g_Bfrag[bbase + (kk * 2 + 0) * 32]);
            uint4 B1 = __ldg(&g_Bfrag[bbase + (kk * 2 + 1) * 32]);
            mma16816(acc,     ah, B0.x, B0.y);
            mma16816(acc,     al, B0.x, B0.y);
            mma16816(acc,     ah, B0.z, B0.w);
            mma16816(acc + 4, ah, B1.x, B1.y);
            mma16816(acc + 4, al, B1.x, B1.y);
            mma16816(acc + 4, ah, B1.z, B1.w);
        }
    }

    // ---- write this CTA's partial ----
    int orow = rb * 128 + w * 16 + (lane >> 2);
    int ocol = (lane & 3) * 2;
    float* gp = g_partial + ((size_t)ms * NN + orow) * OC;
#pragma unroll
    for (int nt = 0; nt < 2; nt++) {
        *(float2*)(gp + nt * 8 + ocol) =
            make_float2(acc[nt * 4 + 0], acc[nt * 4 + 1]);
        *(float2*)(gp + (size_t)8 * OC + nt * 8 + ocol) =
            make_float2(acc[nt * 4 + 2], acc[nt * 4 + 3]);
    }

    // ---- last-arriving CTA for this rowblock sums the MSPLIT partials ----
    __threadfence();
    __syncthreads();
    if (tid == 0) {
        int old = atomicAdd(&g_cnt[rb], 1);
        s_last = (old == MSPLIT - 1);
    }
    __syncthreads();
    if (s_last) {
        __threadfence();
        const float4* base = (const float4*)(g_partial) + (size_t)rb * 128 * (OC / 4);
#pragma unroll
        for (int u = 0; u < 2; u++) {
            int i = tid + u * 256;
            float4 a = base[i];
#pragma unroll
            for (int mc = 1; mc < MSPLIT; mc++) {
                float4 pv = base[(size_t)mc * NN * (OC / 4) + i];
                a.x += pv.x; a.y += pv.y; a.z += pv.z; a.w += pv.w;
            }
            ((float4*)out)[(size_t)rb * 128 * (OC / 4) + i] = a;
        }
        if (tid == 0) g_cnt[rb] = 0;      // self-reset for next graph replay
    }
}

extern "C" void kernel_launch(void* const* d_in, const int* in_sizes, int n_in,
                              void* d_out, int out_size) {
    const float* x    = (const float*)d_in[0];
    const float* w    = (const float*)d_in[1];
    const float* b    = (const float*)d_in[2];
    const float* adj  = (const float*)d_in[3];
    const float* attp = (const float*)d_in[4];
    float* out = (float*)d_out;

    prep_kernel<<<NN / 32, 256>>>(x, w, b, attp);

    cudaFuncSetAttribute(gcn_main, cudaFuncAttributeMaxDynamicSharedMemorySize,
                         DYN_SMEM);

    // PDL launch: gcn_main may start while prep_kernel is still running.
    cudaLaunchConfig_t cfg = {};
    cfg.gridDim = dim3(NN / 128, MSPLIT);
    cfg.blockDim = dim3(256);
    cfg.dynamicSmemBytes = DYN_SMEM;
    cfg.stream = 0;
    cudaLaunchAttribute at[1];
    at[0].id = cudaLaunchAttributeProgrammaticStreamSerialization;
    at[0].val.programmaticStreamSerializationAllowed = 1;
    cfg.attrs = at;
    cfg.numAttrs = 1;
    cudaLaunchKernelEx(&cfg, gcn_main, adj, out);
}